// round 1
// baseline (speedup 1.0000x reference)
#include <cuda_runtime.h>
#include <cuda_bf16.h>
#include <math.h>

// Problem constants
#define BB 32
#define TT 32
#define AD 32
#define HID 1536
#define CATS 32
#define K2 (2*HID)   // 3072

// Scratch (allocation-free rule: __device__ globals)
__device__ float g_x[BB*TT*K2];    // concat([a_emb, tau_emb])  (B*T, 3072)  = 12 MB
__device__ float g_h[BB*TT*HID];   // swish hidden              (B*T, 1536)  = 6 MB

// ---------------------------------------------------------------------------
// Kernel 1: build x = [actions @ W1[cat] + b1, sinusoidal(ts)]
// grid = B*T blocks, 256 threads
// ---------------------------------------------------------------------------
__global__ __launch_bounds__(256) void embed_kernel(
    const float* __restrict__ actions,   // (B,T,32)
    const int*   __restrict__ timesteps, // (B,)
    const int*   __restrict__ cats,      // (B,)
    const float* __restrict__ W1,        // (C,32,HID)
    const float* __restrict__ b1,        // (C,HID)
    float* __restrict__ Xout)            // (B*T, 3072)
{
    int bt = blockIdx.x;
    int b  = bt >> 5;
    __shared__ float sa[AD];
    if (threadIdx.x < AD) sa[threadIdx.x] = actions[bt*AD + threadIdx.x];
    __syncthreads();

    int cat = cats[b];
    const float* Wc = W1 + (size_t)cat * AD * HID;
    const float* bc = b1 + (size_t)cat * HID;
    float ts = (float)timesteps[b];
    float* xrow = Xout + (size_t)bt * K2;

    const float NEG_LN1E4_OVER_HALF = -9.210340371976184f / 768.0f;

    #pragma unroll
    for (int jj = 0; jj < HID/256; jj++) {
        int j = jj*256 + threadIdx.x;
        float acc = bc[j];
        #pragma unroll
        for (int k = 0; k < AD; k++)
            acc += sa[k] * Wc[k*HID + j];
        xrow[j] = acc;

        // tau embedding: interleaved sin/cos, freq index i = j/2
        int i = j >> 1;
        float freq = expf(NEG_LN1E4_OVER_HALF * (float)i);
        float arg = ts * freq;
        xrow[HID + j] = (j & 1) ? cosf(arg) : sinf(arg);
    }
}

// ---------------------------------------------------------------------------
// Kernel 2/3: Y = act( X @ W[cat] + bias[cat] )
// X: (B*T, K) row-major (T=32 rows per sample)
// W: (C, K, HID), bias: (C, HID)
// CTA tile: 32 (M, all T rows of one sample) x 128 (N)
// 256 threads, per-thread 4x4 micro-tile
// grid: (HID/128, B)
// ---------------------------------------------------------------------------
#define TILE_N 128

__global__ __launch_bounds__(256) void gemm_cat(
    const float* __restrict__ X,
    const float* __restrict__ W,
    const float* __restrict__ bias,
    const int*   __restrict__ cats,
    float* __restrict__ Y,
    int K, int applySwish)
{
    __shared__ float sX[32][32];
    __shared__ float sW[32][TILE_N];

    int b  = blockIdx.y;
    int n0 = blockIdx.x * TILE_N;
    int cat = cats[b];
    const float* Xb = X + (size_t)b * TT * K;
    const float* Wc = W + (size_t)cat * K * HID;

    int tx = threadIdx.x & 31;   // n-group: columns n0 + tx*4 .. +3
    int ty = threadIdx.x >> 5;   // m-group: rows ty*4 .. +3

    float acc[4][4];
    #pragma unroll
    for (int i = 0; i < 4; i++)
        #pragma unroll
        for (int j = 0; j < 4; j++) acc[i][j] = 0.0f;

    for (int k0 = 0; k0 < K; k0 += 32) {
        // load X tile: 32x32 = 1024 floats, 4 per thread, coalesced over k
        #pragma unroll
        for (int i = 0; i < 4; i++) {
            int idx = i*256 + threadIdx.x;
            int m = idx >> 5, k = idx & 31;
            sX[m][k] = Xb[(size_t)m*K + k0 + k];
        }
        // load W tile: 32x128 = 4096 floats via float4, 4 per thread
        #pragma unroll
        for (int i = 0; i < 4; i++) {
            int idx = i*256 + threadIdx.x;
            int kr = idx >> 5, c4 = idx & 31;
            float4 w = *reinterpret_cast<const float4*>(
                &Wc[(size_t)(k0 + kr)*HID + n0 + c4*4]);
            *reinterpret_cast<float4*>(&sW[kr][c4*4]) = w;
        }
        __syncthreads();

        #pragma unroll
        for (int kk = 0; kk < 32; kk++) {
            float a0 = sX[ty*4+0][kk];
            float a1 = sX[ty*4+1][kk];
            float a2 = sX[ty*4+2][kk];
            float a3 = sX[ty*4+3][kk];
            float4 w = *reinterpret_cast<const float4*>(&sW[kk][tx*4]);
            acc[0][0] += a0*w.x; acc[0][1] += a0*w.y; acc[0][2] += a0*w.z; acc[0][3] += a0*w.w;
            acc[1][0] += a1*w.x; acc[1][1] += a1*w.y; acc[1][2] += a1*w.z; acc[1][3] += a1*w.w;
            acc[2][0] += a2*w.x; acc[2][1] += a2*w.y; acc[2][2] += a2*w.z; acc[2][3] += a2*w.w;
            acc[3][0] += a3*w.x; acc[3][1] += a3*w.y; acc[3][2] += a3*w.z; acc[3][3] += a3*w.w;
        }
        __syncthreads();
    }

    // epilogue
    int n = n0 + tx*4;
    float4 bv = *reinterpret_cast<const float4*>(&bias[(size_t)cat*HID + n]);
    #pragma unroll
    for (int mi = 0; mi < 4; mi++) {
        int m = ty*4 + mi;
        float4 o;
        o.x = acc[mi][0] + bv.x;
        o.y = acc[mi][1] + bv.y;
        o.z = acc[mi][2] + bv.z;
        o.w = acc[mi][3] + bv.w;
        if (applySwish) {
            o.x = o.x / (1.0f + expf(-o.x));
            o.y = o.y / (1.0f + expf(-o.y));
            o.z = o.z / (1.0f + expf(-o.z));
            o.w = o.w / (1.0f + expf(-o.w));
        }
        *reinterpret_cast<float4*>(&Y[((size_t)b*TT + m)*HID + n]) = o;
    }
}

// ---------------------------------------------------------------------------
extern "C" void kernel_launch(void* const* d_in, const int* in_sizes, int n_in,
                              void* d_out, int out_size)
{
    const float* actions   = (const float*)d_in[0];
    const int*   timesteps = (const int*)  d_in[1];
    const int*   cat_ids   = (const int*)  d_in[2];
    const float* W1        = (const float*)d_in[3];
    const float* b1        = (const float*)d_in[4];
    const float* W2        = (const float*)d_in[5];
    const float* b2        = (const float*)d_in[6];
    const float* W3        = (const float*)d_in[7];
    const float* b3        = (const float*)d_in[8];
    float* out = (float*)d_out;

    float *xp = nullptr, *hp = nullptr;
    cudaGetSymbolAddress((void**)&xp, g_x);
    cudaGetSymbolAddress((void**)&hp, g_h);

    // 1) x = [a_emb, tau_emb]
    embed_kernel<<<BB*TT, 256>>>(actions, timesteps, cat_ids, W1, b1, xp);

    // 2) h = swish(x @ W2[cat] + b2)
    gemm_cat<<<dim3(HID/TILE_N, BB), 256>>>(xp, W2, b2, cat_ids, hp, K2, 1);

    // 3) out = h @ W3[cat] + b3
    gemm_cat<<<dim3(HID/TILE_N, BB), 256>>>(hp, W3, b3, cat_ids, out, HID, 0);
}

// round 2
// speedup vs baseline: 1.5451x; 1.5451x over previous
#include <cuda_runtime.h>
#include <cuda_bf16.h>
#include <math.h>
#include <stdint.h>

// Problem constants
#define BB 32
#define TT 32
#define AD 32
#define HID 1536
#define K2 (2*HID)   // 3072

// Scratch (allocation-free rule: __device__ globals)
__device__ float g_x[BB*TT*K2];    // concat([a_emb, tau_emb])  (B*T, 3072)
__device__ float g_h[BB*TT*HID];   // swish hidden              (B*T, 1536)

// ---------------------------------------------------------------------------
// Kernel 1: build x = [actions @ W1[cat] + b1, sinusoidal(ts)]
// ---------------------------------------------------------------------------
__global__ __launch_bounds__(256) void embed_kernel(
    const float* __restrict__ actions,
    const int*   __restrict__ timesteps,
    const int*   __restrict__ cats,
    const float* __restrict__ W1,
    const float* __restrict__ b1,
    float* __restrict__ Xout)
{
    int bt = blockIdx.x;
    int b  = bt >> 5;
    __shared__ float sa[AD];
    if (threadIdx.x < AD) sa[threadIdx.x] = actions[bt*AD + threadIdx.x];
    __syncthreads();

    int cat = cats[b];
    const float* Wc = W1 + (size_t)cat * AD * HID;
    const float* bc = b1 + (size_t)cat * HID;
    float ts = (float)timesteps[b];
    float* xrow = Xout + (size_t)bt * K2;

    const float NEG_LN1E4_OVER_HALF = -9.210340371976184f / 768.0f;

    #pragma unroll
    for (int jj = 0; jj < HID/256; jj++) {
        int j = jj*256 + threadIdx.x;
        float acc = bc[j];
        #pragma unroll
        for (int k = 0; k < AD; k++)
            acc += sa[k] * Wc[k*HID + j];
        xrow[j] = acc;

        int i = j >> 1;
        float freq = expf(NEG_LN1E4_OVER_HALF * (float)i);
        float arg = ts * freq;
        xrow[HID + j] = (j & 1) ? cosf(arg) : sinf(arg);
    }
}

// ---------------------------------------------------------------------------
// Kernel 2/3: tensor-core GEMM, bf16 hi/lo split (3 mma chains -> fp32 accuracy)
// Y(b*32+m, n) = act( sum_k X[b*32+m, k] * W[cat][k, n] + bias[cat][n] )
// CTA: M=32 (one sample) x N=128.  256 threads = 8 warps.
//   warp: mtile = w&1 (16 rows), nquad = w>>1 (4 n8-tiles = 32 cols)
// ---------------------------------------------------------------------------
#define PADX 40    // sX row stride (elems): 80B rows -> conflict-free ldmatrix
#define PADW 136   // sW row stride (elems): 272B rows -> conflict-free ldmatrix

#define MMA_BF16(d, a0,a1,a2,a3, b0,b1) \
  asm volatile("mma.sync.aligned.m16n8k16.row.col.f32.bf16.bf16.f32 " \
               "{%0,%1,%2,%3}, {%4,%5,%6,%7}, {%8,%9}, {%0,%1,%2,%3};" \
               : "+f"(d[0]),"+f"(d[1]),"+f"(d[2]),"+f"(d[3]) \
               : "r"(a0),"r"(a1),"r"(a2),"r"(a3),"r"(b0),"r"(b1))

#define LDSM_X4(r0,r1,r2,r3, addr) \
  asm volatile("ldmatrix.sync.aligned.m8n8.x4.shared.b16 {%0,%1,%2,%3}, [%4];" \
               : "=r"(r0),"=r"(r1),"=r"(r2),"=r"(r3) : "r"(addr))

#define LDSM_X2T(r0,r1, addr) \
  asm volatile("ldmatrix.sync.aligned.m8n8.x2.trans.shared.b16 {%0,%1}, [%2];" \
               : "=r"(r0),"=r"(r1) : "r"(addr))

__device__ __forceinline__ uint32_t pack_hi2(float v0, float v1) {
    __nv_bfloat162 p = __floats2bfloat162_rn(v0, v1);
    return *reinterpret_cast<uint32_t*>(&p);
}

__global__ __launch_bounds__(256,2) void gemm_cat_mma(
    const float* __restrict__ X,
    const float* __restrict__ W,
    const float* __restrict__ bias,
    const int*   __restrict__ cats,
    float* __restrict__ Y,
    int K, int applySwish)
{
    __shared__ __nv_bfloat16 sXhi[32*PADX], sXlo[32*PADX];
    __shared__ __nv_bfloat16 sWhi[32*PADW], sWlo[32*PADW];

    int b   = blockIdx.y;
    int n0  = blockIdx.x * 128;
    int cat = cats[b];
    const float* Xb = X + (size_t)b * TT * K;
    const float* Wc = W + (size_t)cat * K * HID;

    int tid   = threadIdx.x;
    int lane  = tid & 31;
    int warp  = tid >> 5;
    int mtile = warp & 1;        // rows mtile*16 .. +15
    int nquad = warp >> 1;       // n8-tiles nquad*4 .. +3

    float acc[4][4];
    #pragma unroll
    for (int t = 0; t < 4; t++)
        #pragma unroll
        for (int j = 0; j < 4; j++) acc[t][j] = 0.0f;

    // shared-space base addresses for ldmatrix
    uint32_t aXhi = (uint32_t)__cvta_generic_to_shared(sXhi);
    uint32_t aXlo = (uint32_t)__cvta_generic_to_shared(sXlo);
    uint32_t aWhi = (uint32_t)__cvta_generic_to_shared(sWhi);
    uint32_t aWlo = (uint32_t)__cvta_generic_to_shared(sWlo);

    int lr15 = lane & 15;
    int hiK8 = ((lane >> 4) & 1) * 8;
    int mbase = mtile * 16;

    // register prefetch buffers
    float4 wreg[4];
    float  xreg[4];

    // prologue loads for k0 = 0
    #pragma unroll
    for (int i = 0; i < 4; i++) {
        int idx = i*256 + tid;
        int kr = idx >> 5, c4 = idx & 31;
        wreg[i] = *reinterpret_cast<const float4*>(&Wc[(size_t)kr*HID + n0 + c4*4]);
    }
    #pragma unroll
    for (int i = 0; i < 4; i++) {
        int idx = i*256 + tid;
        int m = idx >> 5, k = idx & 31;
        xreg[i] = Xb[(size_t)m*K + k];
    }

    #pragma unroll 1
    for (int k0 = 0; k0 < K; k0 += 32) {
        // ---- stage current tile: fp32 -> bf16 hi/lo ----
        #pragma unroll
        for (int i = 0; i < 4; i++) {
            int idx = i*256 + tid;
            int m = idx >> 5, k = idx & 31;
            float v = xreg[i];
            __nv_bfloat16 h = __float2bfloat16_rn(v);
            float lof = v - __bfloat162float(h);
            sXhi[m*PADX + k] = h;
            sXlo[m*PADX + k] = __float2bfloat16_rn(lof);
        }
        #pragma unroll
        for (int i = 0; i < 4; i++) {
            int idx = i*256 + tid;
            int kr = idx >> 5, c4 = idx & 31;
            float v[4] = {wreg[i].x, wreg[i].y, wreg[i].z, wreg[i].w};
            __nv_bfloat16 h0 = __float2bfloat16_rn(v[0]);
            __nv_bfloat16 h1 = __float2bfloat16_rn(v[1]);
            __nv_bfloat16 h2 = __float2bfloat16_rn(v[2]);
            __nv_bfloat16 h3 = __float2bfloat16_rn(v[3]);
            uint2 hv, lv;
            hv.x = pack_hi2(v[0], v[1]);
            hv.y = pack_hi2(v[2], v[3]);
            lv.x = pack_hi2(v[0]-__bfloat162float(h0), v[1]-__bfloat162float(h1));
            lv.y = pack_hi2(v[2]-__bfloat162float(h2), v[3]-__bfloat162float(h3));
            *reinterpret_cast<uint2*>(&sWhi[kr*PADW + c4*4]) = hv;
            *reinterpret_cast<uint2*>(&sWlo[kr*PADW + c4*4]) = lv;
        }
        __syncthreads();

        // ---- prefetch next tile while computing ----
        if (k0 + 32 < K) {
            #pragma unroll
            for (int i = 0; i < 4; i++) {
                int idx = i*256 + tid;
                int kr = idx >> 5, c4 = idx & 31;
                wreg[i] = *reinterpret_cast<const float4*>(
                    &Wc[(size_t)(k0 + 32 + kr)*HID + n0 + c4*4]);
            }
            #pragma unroll
            for (int i = 0; i < 4; i++) {
                int idx = i*256 + tid;
                int m = idx >> 5, k = idx & 31;
                xreg[i] = Xb[(size_t)m*K + k0 + 32 + k];
            }
        }

        // ---- compute: 2 k16 steps, 4 n8-tiles, 3 mma chains ----
        #pragma unroll
        for (int ks = 0; ks < 2; ks++) {
            uint32_t ah0,ah1,ah2,ah3, al0,al1,al2,al3;
            uint32_t aoff = (uint32_t)(((mbase + lr15)*PADX + ks*16 + hiK8) * 2);
            LDSM_X4(ah0,ah1,ah2,ah3, aXhi + aoff);
            LDSM_X4(al0,al1,al2,al3, aXlo + aoff);

            #pragma unroll
            for (int t = 0; t < 4; t++) {
                int ntile8 = (nquad*4 + t) * 8;
                uint32_t boff = (uint32_t)(((ks*16 + lr15)*PADW + ntile8) * 2);
                uint32_t bh0,bh1, bl0,bl1;
                LDSM_X2T(bh0,bh1, aWhi + boff);
                LDSM_X2T(bl0,bl1, aWlo + boff);
                MMA_BF16(acc[t], ah0,ah1,ah2,ah3, bh0,bh1);
                MMA_BF16(acc[t], ah0,ah1,ah2,ah3, bl0,bl1);
                MMA_BF16(acc[t], al0,al1,al2,al3, bh0,bh1);
            }
        }
        __syncthreads();
    }

    // ---- epilogue: bias + optional swish, write fp32 ----
    int r  = lane >> 2;
    int nc = (lane & 3) * 2;
    #pragma unroll
    for (int t = 0; t < 4; t++) {
        int nl = (nquad*4 + t)*8 + nc;
        float2 bv = *reinterpret_cast<const float2*>(&bias[(size_t)cat*HID + n0 + nl]);
        float y0 = acc[t][0] + bv.x;
        float y1 = acc[t][1] + bv.y;
        float y2 = acc[t][2] + bv.x;
        float y3 = acc[t][3] + bv.y;
        if (applySwish) {
            y0 = y0 / (1.0f + expf(-y0));
            y1 = y1 / (1.0f + expf(-y1));
            y2 = y2 / (1.0f + expf(-y2));
            y3 = y3 / (1.0f + expf(-y3));
        }
        int row0 = mbase + r;
        float2 o01 = {y0, y1};
        float2 o23 = {y2, y3};
        *reinterpret_cast<float2*>(&Y[((size_t)b*TT + row0    )*HID + n0 + nl]) = o01;
        *reinterpret_cast<float2*>(&Y[((size_t)b*TT + row0 + 8)*HID + n0 + nl]) = o23;
    }
}

// ---------------------------------------------------------------------------
extern "C" void kernel_launch(void* const* d_in, const int* in_sizes, int n_in,
                              void* d_out, int out_size)
{
    const float* actions   = (const float*)d_in[0];
    const int*   timesteps = (const int*)  d_in[1];
    const int*   cat_ids   = (const int*)  d_in[2];
    const float* W1        = (const float*)d_in[3];
    const float* b1        = (const float*)d_in[4];
    const float* W2        = (const float*)d_in[5];
    const float* b2        = (const float*)d_in[6];
    const float* W3        = (const float*)d_in[7];
    const float* b3        = (const float*)d_in[8];
    float* out = (float*)d_out;

    float *xp = nullptr, *hp = nullptr;
    cudaGetSymbolAddress((void**)&xp, g_x);
    cudaGetSymbolAddress((void**)&hp, g_h);

    // 1) x = [a_emb, tau_emb]
    embed_kernel<<<BB*TT, 256>>>(actions, timesteps, cat_ids, W1, b1, xp);

    // 2) h = swish(x @ W2[cat] + b2)
    gemm_cat_mma<<<dim3(HID/128, BB), 256>>>(xp, W2, b2, cat_ids, hp, K2, 1);

    // 3) out = h @ W3[cat] + b3
    gemm_cat_mma<<<dim3(HID/128, BB), 256>>>(hp, W3, b3, cat_ids, out, HID, 0);
}